// round 8
// baseline (speedup 1.0000x reference)
#include <cuda_runtime.h>
#include <cuda_fp16.h>
#include <cstdint>
#include <cstddef>

#define LR_C   0.001f
#define TAU_C  1000.0f

// GEMM tiling: 128x256 CTA tile, 8 warps (2x4), warp tile 64x64, fp16 BKT=64
#define BM 128
#define BN 256
#define BKT 64
#define NSTAGES 4
#define A_BYTES (BM * 128)                   // 16 KB (128 rows x 64 halves)
#define B_BYTES (BN * 128)                   // 32 KB
#define STAGE_BYTES (A_BYTES + B_BYTES)      // 48 KB
#define SMEM_TOTAL (NSTAGES * STAGE_BYTES)   // 192 KB -> 1 CTA/SM, deep pipe
#define RSPLIT 64                            // = DIM_B / BM

// Fixed problem shape: B=8192, IN=OUT=4096.
#define DIM_B   8192
#define DIM_IO  4096

// Scratch (__device__ globals: the sanctioned alloc-free workaround)
__device__ __half g_xr[(size_t)DIM_B * DIM_IO];   // rn(x)            B x IN
__device__ __half g_wr[(size_t)DIM_IO * DIM_IO];  // rn(w)            OUT x IN
__device__ __half g_xt[(size_t)DIM_IO * DIM_B];   // rn(x)^T          IN x B
__device__ __half g_pt[(size_t)DIM_IO * DIM_B];   // rn(relu(o-th))^T OUT x B
__device__ float  g_partial[RSPLIT * DIM_IO];

// ---------------------------------------------------------------------------
// PTX helpers (baseline sm_80+ features ONLY)
// ---------------------------------------------------------------------------
__device__ __forceinline__ uint32_t smem_u32(const void* p) {
    return (uint32_t)__cvta_generic_to_shared(p);
}

__device__ __forceinline__ void cp_async16(uint32_t s, const void* g) {
    asm volatile("cp.async.cg.shared.global [%0], [%1], 16;\n" :: "r"(s), "l"(g));
}
#define CP_COMMIT() asm volatile("cp.async.commit_group;\n" ::)
#define CP_WAIT2()  asm volatile("cp.async.wait_group 2;\n" ::: "memory")

__device__ __forceinline__ void ldsm_x4(uint32_t* r, uint32_t addr) {
    asm volatile("ldmatrix.sync.aligned.m8n8.x4.shared.b16 {%0,%1,%2,%3}, [%4];"
                 : "=r"(r[0]), "=r"(r[1]), "=r"(r[2]), "=r"(r[3]) : "r"(addr));
}

__device__ __forceinline__ uint32_t sw128(uint32_t off) {
    return off ^ ((off >> 3) & 0x70);
}

// m16n8k16 fp16 MMA, fp32 accumulate
__device__ __forceinline__ void mma_16816(float* c, const uint32_t* a,
                                          uint32_t b0, uint32_t b1) {
    asm volatile(
        "mma.sync.aligned.m16n8k16.row.col.f32.f16.f16.f32 "
        "{%0,%1,%2,%3}, {%4,%5,%6,%7}, {%8,%9}, {%0,%1,%2,%3};"
        : "+f"(c[0]), "+f"(c[1]), "+f"(c[2]), "+f"(c[3])
        : "r"(a[0]), "r"(a[1]), "r"(a[2]), "r"(a[3]), "r"(b0), "r"(b1));
}

// ---------------------------------------------------------------------------
// FP16 tensor-core GEMM: C[M,N] = A[M,K] * B[N,K]^T (both K-major half)
// mode 0: C = D, and fused per-CTA column sums -> g_partial[blockIdx.y][col]
// mode 1: C = Wold + scale * D
// SMEM layout: rows of 128 bytes (64 halves = one BKT slice), SW128 swizzle.
// ---------------------------------------------------------------------------
__device__ __forceinline__ void load_stage(uint32_t smem_base, int stage,
                                           const __half* Ab, const __half* Bb,
                                           int K, int k0, int tid) {
    uint32_t sa = smem_base + stage * STAGE_BYTES;
    uint32_t sb = sa + A_BYTES;
    #pragma unroll
    for (int i = 0; i < 4; i++) {            // A: 128 rows x 8 x 16B chunks
        int idx = tid + i * 256;
        int row = idx >> 3, c = idx & 7;
        cp_async16(sa + sw128((uint32_t)(row * 128 + c * 16)),
                   (const char*)(Ab + (size_t)row * K + k0) + c * 16);
    }
    #pragma unroll
    for (int i = 0; i < 8; i++) {            // B: 256 rows x 8 x 16B chunks
        int idx = tid + i * 256;
        int row = idx >> 3, c = idx & 7;
        cp_async16(sb + sw128((uint32_t)(row * 128 + c * 16)),
                   (const char*)(Bb + (size_t)row * K + k0) + c * 16);
    }
}

__global__ __launch_bounds__(256, 1) void gemm_mma_kernel(
    const __half* __restrict__ A, const __half* __restrict__ Bmat,
    const float* __restrict__ Wold, float* __restrict__ C,
    int M, int N, int K, float scale, int mode)
{
    extern __shared__ char smem[];
    const uint32_t smem_base = smem_u32(smem);
    const int tid  = threadIdx.x;
    const int warp = tid >> 5, lane = tid & 31;
    const int wm = warp >> 2, wn = warp & 3;       // 2 x 4 warp grid, 64x64 each
    const int lr = lane >> 2, lc = lane & 3;

    const int mbase = blockIdx.y * BM;
    const int nbase = blockIdx.x * BN;
    const __half* Ab = A + (size_t)mbase * K;
    const __half* Bb = Bmat + (size_t)nbase * K;

    // ldmatrix addressing (128B smem rows, 16B chunks, swizzle mask (lane&7)<<4)
    const uint32_t swz_mask = (uint32_t)((lane & 7) << 4);
    // A x4: mat0 m+0 k0-7 | mat1 m+8 k0-7 | mat2 m+0 k8-15 | mat3 m+8 k8-15
    const int arow = wm * 64 + ((lane >> 3) & 1) * 8 + (lane & 7);
    const uint32_t a_kb = (uint32_t)((lane >> 4) * 16);
    uint32_t a_rowoff[4];
    #pragma unroll
    for (int mt = 0; mt < 4; mt++) a_rowoff[mt] = (uint32_t)((arow + mt * 16) * 128);
    // B x4 (pair p covers n-tiles 2p,2p+1): mat0 n+0 k0-7 | mat1 n+0 k8-15 | mat2 n+8 k0-7 | mat3 n+8 k8-15
    const int brow = wn * 64 + ((lane >> 4) & 1) * 8 + (lane & 7);
    const uint32_t b_kb = (uint32_t)(((lane >> 3) & 1) * 16);
    uint32_t b_rowoff[4];
    #pragma unroll
    for (int p = 0; p < 4; p++) b_rowoff[p] = (uint32_t)((brow + p * 16) * 128);

    float acc[4][8][4];                            // [mt][nt][frag]
    #pragma unroll
    for (int i = 0; i < 4; i++)
        #pragma unroll
        for (int j = 0; j < 8; j++)
            #pragma unroll
            for (int f = 0; f < 4; f++) acc[i][j][f] = 0.f;

    const int niter = K / BKT;

    // Prologue: 3 stages in flight
    #pragma unroll
    for (int s = 0; s < 3; s++) {
        load_stage(smem_base, s, Ab, Bb, K, s * BKT, tid);
        CP_COMMIT();
    }

    int buf = 0;
    for (int it = 0; it < niter; ++it) {
        CP_WAIT2();            // stage `it` resident (<=2 newer groups pending)
        __syncthreads();
        uint32_t sa = smem_base + buf * STAGE_BYTES;
        uint32_t sb = sa + A_BYTES;

        #pragma unroll
        for (int ks = 0; ks < BKT / 16; ks++) {    // 4 k16-steps, 32B stride each
            const uint32_t xa = ((uint32_t)(ks * 32) + a_kb) ^ swz_mask;
            const uint32_t xb = ((uint32_t)(ks * 32) + b_kb) ^ swz_mask;
            uint32_t a[4][4], b[4][4];
            #pragma unroll
            for (int mt = 0; mt < 4; mt++) ldsm_x4(a[mt], sa + a_rowoff[mt] + xa);
            #pragma unroll
            for (int p = 0; p < 4; p++)    ldsm_x4(b[p], sb + b_rowoff[p] + xb);
            #pragma unroll
            for (int mt = 0; mt < 4; mt++) {
                #pragma unroll
                for (int p = 0; p < 4; p++) {
                    mma_16816(acc[mt][2 * p],     a[mt], b[p][0], b[p][1]);
                    mma_16816(acc[mt][2 * p + 1], a[mt], b[p][2], b[p][3]);
                }
            }
        }

        const int itn = it + 3;
        if (itn < niter)
            load_stage(smem_base, itn & 3, Ab, Bb, K, itn * BKT, tid);
        CP_COMMIT();           // uniform group count even when no loads issued
        buf = (buf + 1) & 3;
    }

    // Epilogue: per thread 4x8 tiles, two float2 rows each
    #pragma unroll
    for (int mt = 0; mt < 4; mt++) {
        int r0 = mbase + wm * 64 + mt * 16 + lr;
        #pragma unroll
        for (int nt = 0; nt < 8; nt++) {
            int cc = nbase + wn * 64 + nt * 8 + lc * 2;
            size_t i0 = (size_t)r0 * N + cc;
            size_t i1 = (size_t)(r0 + 8) * N + cc;
            if (mode == 0) {
                *(float2*)(C + i0) = make_float2(acc[mt][nt][0], acc[mt][nt][1]);
                *(float2*)(C + i1) = make_float2(acc[mt][nt][2], acc[mt][nt][3]);
            } else {
                float2 w0 = *(const float2*)(Wold + i0);
                float2 w1 = *(const float2*)(Wold + i1);
                w0.x += scale * acc[mt][nt][0]; w0.y += scale * acc[mt][nt][1];
                w1.x += scale * acc[mt][nt][2]; w1.y += scale * acc[mt][nt][3];
                *(float2*)(C + i0) = w0;
                *(float2*)(C + i1) = w1;
            }
        }
    }

    // Fused column partial sums for threshold EMA (mode 0 only, deterministic):
    // each CTA reduces its 128 rows; g_partial[blockIdx.y * N + col] = sum.
    if (mode == 0) {
        float s0[8], s1[8];
        #pragma unroll
        for (int nt = 0; nt < 8; nt++) {
            float a0 = 0.f, a1 = 0.f;
            #pragma unroll
            for (int mt = 0; mt < 4; mt++) {
                a0 += acc[mt][nt][0] + acc[mt][nt][2];
                a1 += acc[mt][nt][1] + acc[mt][nt][3];
            }
            // reduce over lr (lanes xor 4, 8, 16)
            #pragma unroll
            for (int off = 4; off <= 16; off <<= 1) {
                a0 += __shfl_xor_sync(0xffffffffu, a0, off);
                a1 += __shfl_xor_sync(0xffffffffu, a1, off);
            }
            s0[nt] = a0; s1[nt] = a1;
        }
        // cross-warp (wm) combine via smem (alias stage buffers; all reads done)
        float* csum = (float*)smem;           // 256 floats
        __syncthreads();
        if (wm == 1 && lr == 0) {
            #pragma unroll
            for (int nt = 0; nt < 8; nt++) {
                int col = wn * 64 + nt * 8 + lc * 2;
                csum[col] = s0[nt]; csum[col + 1] = s1[nt];
            }
        }
        __syncthreads();
        if (wm == 0 && lr == 0) {
            #pragma unroll
            for (int nt = 0; nt < 8; nt++) {
                int col = wn * 64 + nt * 8 + lc * 2;
                size_t gi = (size_t)blockIdx.y * N + nbase + col;
                g_partial[gi]     = s0[nt] + csum[col];
                g_partial[gi + 1] = s1[nt] + csum[col + 1];
            }
        }
    }
}

// ---------------------------------------------------------------------------
// Prep kernels
// ---------------------------------------------------------------------------
__global__ void h_kernel(const float* __restrict__ in, __half* __restrict__ out, size_t n4) {
    size_t i = (size_t)blockIdx.x * blockDim.x + threadIdx.x;
    if (i < n4) {
        float4 v = ((const float4*)in)[i];
        ((__half2*)out)[2 * i]     = __floats2half2_rn(v.x, v.y);
        ((__half2*)out)[2 * i + 1] = __floats2half2_rn(v.z, v.w);
    }
}

// One pass over x: XR[b][i] = rn(x[b][i]); XT[i][b] = rn(x[b][i])
__global__ void prep_x_kernel(const float* __restrict__ X, __half* __restrict__ XR,
                              __half* __restrict__ XT, int Bn, int INn) {
    __shared__ float t[32][33];
    int b0 = blockIdx.x * 32, i0 = blockIdx.y * 32;
    int tx = threadIdx.x, ty = threadIdx.y;
    for (int r = ty; r < 32; r += 8) {
        float v = X[(size_t)(b0 + r) * INn + i0 + tx];
        t[r][tx] = v;
        XR[(size_t)(b0 + r) * INn + i0 + tx] = __float2half_rn(v);
    }
    __syncthreads();
    for (int r = ty; r < 32; r += 8)
        XT[(size_t)(i0 + r) * Bn + b0 + tx] = __float2half_rn(t[tx][r]);
}

// PT[o][b] = rn(max(O[b][o] - th[o], 0))
__global__ void pt_kernel(const float* __restrict__ O, const float* __restrict__ th,
                          __half* __restrict__ PT, int Bn, int OUTn) {
    __shared__ float t[32][33];
    int b0 = blockIdx.x * 32, o0 = blockIdx.y * 32;
    int tx = threadIdx.x, ty = threadIdx.y;
    for (int r = ty; r < 32; r += 8)
        t[r][tx] = O[(size_t)(b0 + r) * OUTn + o0 + tx];
    __syncthreads();
    for (int r = ty; r < 32; r += 8) {
        float thv = __ldg(th + o0 + r);
        PT[(size_t)(o0 + r) * Bn + b0 + tx] = __float2half_rn(fmaxf(t[tx][r] - thv, 0.f));
    }
}

__global__ void thresh_kernel(const float* __restrict__ th_old,
                              float* __restrict__ th_new, int Bn, int OUTn) {
    int c = blockIdx.x * blockDim.x + threadIdx.x;
    if (c >= OUTn) return;
    float s = 0.f;
    #pragma unroll 8
    for (int p = 0; p < RSPLIT; p++) s += g_partial[p * OUTn + c];
    float act = s / (float)Bn;
    float t = th_old[c];
    th_new[c] = t + (act * act - t) / TAU_C;
}

// ---------------------------------------------------------------------------
extern "C" void kernel_launch(void* const* d_in, const int* in_sizes, int n_in,
                              void* d_out, int out_size)
{
    const float* x  = (const float*)d_in[0];
    const float* w  = (const float*)d_in[1];
    const float* th = (const float*)d_in[2];

    const int OUT = in_sizes[2];
    const int IN  = in_sizes[1] / OUT;
    const int Bn  = in_sizes[0] / IN;

    float* out    = (float*)d_out;
    float* out_O  = out;                          // B x OUT
    float* out_th = out + (size_t)Bn * OUT;       // OUT
    float* out_W  = out_th + OUT;                 // OUT x IN

    void *p;
    cudaGetSymbolAddress(&p, g_xr); __half* XR = (__half*)p;
    cudaGetSymbolAddress(&p, g_wr); __half* WR = (__half*)p;
    cudaGetSymbolAddress(&p, g_xt); __half* XT = (__half*)p;
    cudaGetSymbolAddress(&p, g_pt); __half* PT = (__half*)p;

    cudaFuncSetAttribute(gemm_mma_kernel,
                         cudaFuncAttributeMaxDynamicSharedMemorySize, SMEM_TOTAL);

    // Convert operands to fp16 (RN, unbiased; same 10-bit mantissa as tf32)
    size_t nW = (size_t)OUT * IN;
    prep_x_kernel<<<dim3(Bn / 32, IN / 32), dim3(32, 8)>>>(x, XR, XT, Bn, IN);
    h_kernel<<<(unsigned)((nW / 4 + 255) / 256), 256>>>(w, WR, nW / 4);

    // 1) O = X @ W^T   (M=B, N=OUT, K=IN), fused column partials
    dim3 g1(OUT / BN, Bn / BM);
    gemm_mma_kernel<<<g1, 256, SMEM_TOTAL>>>(XR, WR, nullptr, out_O,
                                             Bn, OUT, IN, 0.f, 0);

    // 2) threshold EMA (partials already produced by GEMM1)
    thresh_kernel<<<(OUT + 255) / 256, 256>>>(th, out_th, Bn, OUT);

    // 3) PT = relu(O - th)^T ; Wnew = W + (LR/B) * PT @ XT^T  (M=OUT, N=IN, K=B)
    pt_kernel<<<dim3(Bn / 32, OUT / 32), dim3(32, 8)>>>(out_O, out_th, PT, Bn, OUT);
    dim3 g2(IN / BN, OUT / BM);
    gemm_mma_kernel<<<g2, 256, SMEM_TOTAL>>>(PT, XT, w, out_W,
                                             OUT, IN, Bn, LR_C / (float)Bn, 1);
}

// round 9
// speedup vs baseline: 1.1301x; 1.1301x over previous
#include <cuda_runtime.h>
#include <cuda_fp16.h>
#include <cstdint>
#include <cstddef>

#define LR_C   0.001f
#define TAU_C  1000.0f

// GEMM tiling: 128x128 CTA tile, 4 warps (2x2), warp tile 64x64, fp16 BKT=64
#define BM 128
#define BN 128
#define BKT 64
#define NSTAGES 3
#define A_BYTES (BM * 128)                   // 16 KB (128 rows x 64 halves)
#define STAGE_BYTES (2 * A_BYTES)            // 32 KB
#define SMEM_TOTAL (NSTAGES * STAGE_BYTES)   // 96 KB -> 2 CTA/SM
#define RSPLIT 64                            // = DIM_B / BM

// Fixed problem shape: B=8192, IN=OUT=4096.
#define DIM_B   8192
#define DIM_IO  4096

// Scratch (__device__ globals: the sanctioned alloc-free workaround)
__device__ __half g_xr[(size_t)DIM_B * DIM_IO];   // rn(x)            B x IN
__device__ __half g_wr[(size_t)DIM_IO * DIM_IO];  // rn(w)            OUT x IN
__device__ __half g_xt[(size_t)DIM_IO * DIM_B];   // rn(x)^T          IN x B
__device__ __half g_pt[(size_t)DIM_IO * DIM_B];   // rn(relu(o-th))^T OUT x B
__device__ float  g_partial[RSPLIT * DIM_IO];

// ---------------------------------------------------------------------------
// PTX helpers (baseline sm_80+ features ONLY)
// ---------------------------------------------------------------------------
__device__ __forceinline__ uint32_t smem_u32(const void* p) {
    return (uint32_t)__cvta_generic_to_shared(p);
}

__device__ __forceinline__ void cp_async16(uint32_t s, const void* g) {
    asm volatile("cp.async.cg.shared.global [%0], [%1], 16;\n" :: "r"(s), "l"(g));
}
#define CP_COMMIT() asm volatile("cp.async.commit_group;\n" ::)
#define CP_WAIT1()  asm volatile("cp.async.wait_group 1;\n" ::: "memory")

__device__ __forceinline__ void ldsm_x4(uint32_t* r, uint32_t addr) {
    asm volatile("ldmatrix.sync.aligned.m8n8.x4.shared.b16 {%0,%1,%2,%3}, [%4];"
                 : "=r"(r[0]), "=r"(r[1]), "=r"(r[2]), "=r"(r[3]) : "r"(addr));
}

__device__ __forceinline__ uint32_t sw128(uint32_t off) {
    return off ^ ((off >> 3) & 0x70);
}

// m16n8k16 fp16 MMA, fp32 accumulate
__device__ __forceinline__ void mma_16816(float* c, const uint32_t* a,
                                          uint32_t b0, uint32_t b1) {
    asm volatile(
        "mma.sync.aligned.m16n8k16.row.col.f32.f16.f16.f32 "
        "{%0,%1,%2,%3}, {%4,%5,%6,%7}, {%8,%9}, {%0,%1,%2,%3};"
        : "+f"(c[0]), "+f"(c[1]), "+f"(c[2]), "+f"(c[3])
        : "r"(a[0]), "r"(a[1]), "r"(a[2]), "r"(a[3]), "r"(b0), "r"(b1));
}

// ---------------------------------------------------------------------------
// FP16 tensor-core GEMM: C[M,N] = A[M,K] * B[N,K]^T (both K-major half)
// mode 0: C = D, and fused per-CTA column sums -> g_partial[blockIdx.y][col]
// mode 1: C = Wold + scale * D
// SMEM layout: 128 rows x 128 bytes (64 halves = one BKT slice), SW128 swizzle.
// ---------------------------------------------------------------------------
__device__ __forceinline__ void load_stage(uint32_t smem_base, int stage,
                                           const __half* Ab, const __half* Bb,
                                           int K, int k0, int tid) {
    uint32_t sa = smem_base + stage * STAGE_BYTES;
    uint32_t sb = sa + A_BYTES;
    #pragma unroll
    for (int i = 0; i < 8; i++) {            // A: 128 rows x 8 x 16B chunks
        int idx = tid + i * 128;
        int row = idx >> 3, c = idx & 7;
        cp_async16(sa + sw128((uint32_t)(row * 128 + c * 16)),
                   (const char*)(Ab + (size_t)row * K + k0) + c * 16);
    }
    #pragma unroll
    for (int i = 0; i < 8; i++) {            // B: 128 rows x 8 x 16B chunks
        int idx = tid + i * 128;
        int row = idx >> 3, c = idx & 7;
        cp_async16(sb + sw128((uint32_t)(row * 128 + c * 16)),
                   (const char*)(Bb + (size_t)row * K + k0) + c * 16);
    }
}

__global__ __launch_bounds__(128, 2) void gemm_mma_kernel(
    const __half* __restrict__ A, const __half* __restrict__ Bmat,
    const float* __restrict__ Wold, float* __restrict__ C,
    int M, int N, int K, float scale, int mode)
{
    extern __shared__ char smem[];
    const uint32_t smem_base = smem_u32(smem);
    const int tid  = threadIdx.x;
    const int warp = tid >> 5, lane = tid & 31;
    const int wm = warp >> 1, wn = warp & 1;       // 2 x 2 warp grid, 64x64 each
    const int lr = lane >> 2, lc = lane & 3;

    const int mbase = blockIdx.y * BM;
    const int nbase = blockIdx.x * BN;
    const __half* Ab = A + (size_t)mbase * K;
    const __half* Bb = Bmat + (size_t)nbase * K;

    // ldmatrix addressing (128B smem rows, 16B chunks, swizzle mask (lane&7)<<4)
    const uint32_t swz_mask = (uint32_t)((lane & 7) << 4);
    const int arow = wm * 64 + ((lane >> 3) & 1) * 8 + (lane & 7);
    const uint32_t a_kb = (uint32_t)((lane >> 4) * 16);
    uint32_t a_rowoff[4];
    #pragma unroll
    for (int mt = 0; mt < 4; mt++) a_rowoff[mt] = (uint32_t)((arow + mt * 16) * 128);
    const int brow = wn * 64 + ((lane >> 4) & 1) * 8 + (lane & 7);
    const uint32_t b_kb = (uint32_t)(((lane >> 3) & 1) * 16);
    uint32_t b_rowoff[4];
    #pragma unroll
    for (int p = 0; p < 4; p++) b_rowoff[p] = (uint32_t)((brow + p * 16) * 128);

    float acc[4][8][4];                            // [mt][nt][frag]
    #pragma unroll
    for (int i = 0; i < 4; i++)
        #pragma unroll
        for (int j = 0; j < 8; j++)
            #pragma unroll
            for (int f = 0; f < 4; f++) acc[i][j][f] = 0.f;

    const int niter = K / BKT;

    load_stage(smem_base, 0, Ab, Bb, K, 0, tid);   CP_COMMIT();
    load_stage(smem_base, 1, Ab, Bb, K, BKT, tid); CP_COMMIT();

    // Fragment double buffer: load ks+1 while issuing MMAs of ks.
    uint32_t a[2][4][4], b[2][4][4];

    int buf = 0;
    for (int it = 0; it < niter; ++it) {
        CP_WAIT1();
        __syncthreads();
        uint32_t sa = smem_base + buf * STAGE_BYTES;
        uint32_t sb = sa + A_BYTES;

        // prime ks = 0
        {
            const uint32_t xa = a_kb ^ swz_mask;
            const uint32_t xb = b_kb ^ swz_mask;
            #pragma unroll
            for (int mt = 0; mt < 4; mt++) ldsm_x4(a[0][mt], sa + a_rowoff[mt] + xa);
            #pragma unroll
            for (int p = 0; p < 4; p++)    ldsm_x4(b[0][p], sb + b_rowoff[p] + xb);
        }

        #pragma unroll
        for (int ks = 0; ks < BKT / 16; ks++) {    // 4 k16-steps, 32B stride each
            const int cur = ks & 1, nxt = cur ^ 1;
            if (ks < BKT / 16 - 1) {               // prefetch next fragments
                const uint32_t xa = ((uint32_t)((ks + 1) * 32) + a_kb) ^ swz_mask;
                const uint32_t xb = ((uint32_t)((ks + 1) * 32) + b_kb) ^ swz_mask;
                #pragma unroll
                for (int mt = 0; mt < 4; mt++) ldsm_x4(a[nxt][mt], sa + a_rowoff[mt] + xa);
                #pragma unroll
                for (int p = 0; p < 4; p++)    ldsm_x4(b[nxt][p], sb + b_rowoff[p] + xb);
            }
            #pragma unroll
            for (int mt = 0; mt < 4; mt++) {
                #pragma unroll
                for (int p = 0; p < 4; p++) {
                    mma_16816(acc[mt][2 * p],     a[cur][mt], b[cur][p][0], b[cur][p][1]);
                    mma_16816(acc[mt][2 * p + 1], a[cur][mt], b[cur][p][2], b[cur][p][3]);
                }
            }
        }

        const int itn = it + 2;
        if (itn < niter)
            load_stage(smem_base, itn % NSTAGES, Ab, Bb, K, itn * BKT, tid);
        CP_COMMIT();
        buf = (buf + 1 == NSTAGES) ? 0 : buf + 1;
    }

    // Epilogue: per thread 4x8 tiles, two float2 rows each
    #pragma unroll
    for (int mt = 0; mt < 4; mt++) {
        int r0 = mbase + wm * 64 + mt * 16 + lr;
        #pragma unroll
        for (int nt = 0; nt < 8; nt++) {
            int cc = nbase + wn * 64 + nt * 8 + lc * 2;
            size_t i0 = (size_t)r0 * N + cc;
            size_t i1 = (size_t)(r0 + 8) * N + cc;
            if (mode == 0) {
                *(float2*)(C + i0) = make_float2(acc[mt][nt][0], acc[mt][nt][1]);
                *(float2*)(C + i1) = make_float2(acc[mt][nt][2], acc[mt][nt][3]);
            } else {
                float2 w0 = *(const float2*)(Wold + i0);
                float2 w1 = *(const float2*)(Wold + i1);
                w0.x += scale * acc[mt][nt][0]; w0.y += scale * acc[mt][nt][1];
                w1.x += scale * acc[mt][nt][2]; w1.y += scale * acc[mt][nt][3];
                *(float2*)(C + i0) = w0;
                *(float2*)(C + i1) = w1;
            }
        }
    }

    // Fused column partial sums for threshold EMA (mode 0 only, deterministic)
    if (mode == 0) {
        float s0[8], s1[8];
        #pragma unroll
        for (int nt = 0; nt < 8; nt++) {
            float a0 = 0.f, a1 = 0.f;
            #pragma unroll
            for (int mt = 0; mt < 4; mt++) {
                a0 += acc[mt][nt][0] + acc[mt][nt][2];
                a1 += acc[mt][nt][1] + acc[mt][nt][3];
            }
            #pragma unroll
            for (int off = 4; off <= 16; off <<= 1) {
                a0 += __shfl_xor_sync(0xffffffffu, a0, off);
                a1 += __shfl_xor_sync(0xffffffffu, a1, off);
            }
            s0[nt] = a0; s1[nt] = a1;
        }
        float* csum = (float*)smem;           // 128 floats (stage bufs done)
        __syncthreads();
        if (wm == 1 && lr == 0) {
            #pragma unroll
            for (int nt = 0; nt < 8; nt++) {
                int col = wn * 64 + nt * 8 + lc * 2;
                csum[col] = s0[nt]; csum[col + 1] = s1[nt];
            }
        }
        __syncthreads();
        if (wm == 0 && lr == 0) {
            #pragma unroll
            for (int nt = 0; nt < 8; nt++) {
                int col = wn * 64 + nt * 8 + lc * 2;
                size_t gi = (size_t)blockIdx.y * N + nbase + col;
                g_partial[gi]     = s0[nt] + csum[col];
                g_partial[gi + 1] = s1[nt] + csum[col + 1];
            }
        }
    }
}

// ---------------------------------------------------------------------------
// Prep kernels
// ---------------------------------------------------------------------------
__global__ void h_kernel(const float* __restrict__ in, __half* __restrict__ out, size_t n4) {
    size_t i = (size_t)blockIdx.x * blockDim.x + threadIdx.x;
    if (i < n4) {
        float4 v = ((const float4*)in)[i];
        ((__half2*)out)[2 * i]     = __floats2half2_rn(v.x, v.y);
        ((__half2*)out)[2 * i + 1] = __floats2half2_rn(v.z, v.w);
    }
}

// One pass over x: XR[b][i] = rn(x[b][i]); XT[i][b] = rn(x[b][i])
__global__ void prep_x_kernel(const float* __restrict__ X, __half* __restrict__ XR,
                              __half* __restrict__ XT, int Bn, int INn) {
    __shared__ float t[32][33];
    int b0 = blockIdx.x * 32, i0 = blockIdx.y * 32;
    int tx = threadIdx.x, ty = threadIdx.y;
    for (int r = ty; r < 32; r += 8) {
        float v = X[(size_t)(b0 + r) * INn + i0 + tx];
        t[r][tx] = v;
        XR[(size_t)(b0 + r) * INn + i0 + tx] = __float2half_rn(v);
    }
    __syncthreads();
    for (int r = ty; r < 32; r += 8)
        XT[(size_t)(i0 + r) * Bn + b0 + tx] = __float2half_rn(t[tx][r]);
}

// PT[o][b] = rn(max(O[b][o] - th[o], 0))
__global__ void pt_kernel(const float* __restrict__ O, const float* __restrict__ th,
                          __half* __restrict__ PT, int Bn, int OUTn) {
    __shared__ float t[32][33];
    int b0 = blockIdx.x * 32, o0 = blockIdx.y * 32;
    int tx = threadIdx.x, ty = threadIdx.y;
    for (int r = ty; r < 32; r += 8)
        t[r][tx] = O[(size_t)(b0 + r) * OUTn + o0 + tx];
    __syncthreads();
    for (int r = ty; r < 32; r += 8) {
        float thv = __ldg(th + o0 + r);
        PT[(size_t)(o0 + r) * Bn + b0 + tx] = __float2half_rn(fmaxf(t[tx][r] - thv, 0.f));
    }
}

__global__ void thresh_kernel(const float* __restrict__ th_old,
                              float* __restrict__ th_new, int Bn, int OUTn) {
    int c = blockIdx.x * blockDim.x + threadIdx.x;
    if (c >= OUTn) return;
    float s = 0.f;
    #pragma unroll 8
    for (int p = 0; p < RSPLIT; p++) s += g_partial[p * OUTn + c];
    float act = s / (float)Bn;
    float t = th_old[c];
    th_new[c] = t + (act * act - t) / TAU_C;
}

// ---------------------------------------------------------------------------
extern "C" void kernel_launch(void* const* d_in, const int* in_sizes, int n_in,
                              void* d_out, int out_size)
{
    const float* x  = (const float*)d_in[0];
    const float* w  = (const float*)d_in[1];
    const float* th = (const float*)d_in[2];

    const int OUT = in_sizes[2];
    const int IN  = in_sizes[1] / OUT;
    const int Bn  = in_sizes[0] / IN;

    float* out    = (float*)d_out;
    float* out_O  = out;                          // B x OUT
    float* out_th = out + (size_t)Bn * OUT;       // OUT
    float* out_W  = out_th + OUT;                 // OUT x IN

    void *p;
    cudaGetSymbolAddress(&p, g_xr); __half* XR = (__half*)p;
    cudaGetSymbolAddress(&p, g_wr); __half* WR = (__half*)p;
    cudaGetSymbolAddress(&p, g_xt); __half* XT = (__half*)p;
    cudaGetSymbolAddress(&p, g_pt); __half* PT = (__half*)p;

    cudaFuncSetAttribute(gemm_mma_kernel,
                         cudaFuncAttributeMaxDynamicSharedMemorySize, SMEM_TOTAL);

    // Convert operands to fp16 (RN, unbiased; same 10-bit mantissa as tf32)
    size_t nW = (size_t)OUT * IN;
    prep_x_kernel<<<dim3(Bn / 32, IN / 32), dim3(32, 8)>>>(x, XR, XT, Bn, IN);
    h_kernel<<<(unsigned)((nW / 4 + 255) / 256), 256>>>(w, WR, nW / 4);

    // 1) O = X @ W^T   (M=B, N=OUT, K=IN), fused column partials
    dim3 g1(OUT / BN, Bn / BM);
    gemm_mma_kernel<<<g1, 128, SMEM_TOTAL>>>(XR, WR, nullptr, out_O,
                                             Bn, OUT, IN, 0.f, 0);

    // 2) threshold EMA (partials already produced by GEMM1)
    thresh_kernel<<<(OUT + 255) / 256, 256>>>(th, out_th, Bn, OUT);

    // 3) PT = relu(O - th)^T ; Wnew = W + (LR/B) * PT @ XT^T  (M=OUT, N=IN, K=B)
    pt_kernel<<<dim3(Bn / 32, OUT / 32), dim3(32, 8)>>>(out_O, out_th, PT, Bn, OUT);
    dim3 g2(IN / BN, OUT / BM);
    gemm_mma_kernel<<<g2, 128, SMEM_TOTAL>>>(PT, XT, w, out_W,
                                             OUT, IN, Bn, LR_C / (float)Bn, 1);
}